// round 8
// baseline (speedup 1.0000x reference)
#include <cuda_runtime.h>

// out_half[h] = X[idx_flat[h], :]  for h in [0, 2E)   (512B per half-row)
// Strategy: invert idx (node -> list of h) via counting sort, then one warp
// per node loads its 512B row ONCE into registers and broadcast-stores it to
// all destinations. Cuts LTS gather-read traffic from 328MB (L2-hit reuse)
// to 51MB (one read per row): total LTS ~395MB vs 660MB.

#define D4 32              // float4 per X row (128 floats)
#define N_MAX 131072
#define H_MAX (1 << 20)
#define SCAN_BLK 1024
#define NB_MAX (N_MAX / SCAN_BLK)   // 128

__device__ int g_count[N_MAX];
__device__ int g_base[N_MAX];
__device__ int g_cursor[N_MAX];
__device__ int g_perm[H_MAX];
__device__ int g_bsum[NB_MAX];

__global__ void k_zero(int n) {
    int i = blockIdx.x * blockDim.x + threadIdx.x;
    if (i < n) g_count[i] = 0;
}

__global__ void k_hist(const int* __restrict__ idx, int H) {
    int h = blockIdx.x * blockDim.x + threadIdx.x;
    if (h < H) atomicAdd(&g_count[idx[h]], 1);
}

// Phase A: per-1024-segment sums
__global__ void k_scanA(int n) {
    __shared__ int s[256];
    int b = blockIdx.x, t = threadIdx.x;
    int base = b * SCAN_BLK, sum = 0;
    for (int i = t; i < SCAN_BLK; i += 256) {
        int g = base + i;
        sum += (g < n) ? g_count[g] : 0;
    }
    s[t] = sum; __syncthreads();
    for (int o = 128; o > 0; o >>= 1) {
        if (t < o) s[t] += s[t + o];
        __syncthreads();
    }
    if (t == 0) g_bsum[b] = s[0];
}

// Phase B: exclusive scan of segment sums (<=128 values, trivial)
__global__ void k_scanB(int nb) {
    if (threadIdx.x == 0 && blockIdx.x == 0) {
        int acc = 0;
        for (int i = 0; i < nb; i++) { int v = g_bsum[i]; g_bsum[i] = acc; acc += v; }
    }
}

// Phase C: within-segment exclusive scan + segment offset -> g_base, g_cursor
__global__ void k_scanC(int n) {
    __shared__ int s[256];
    int b = blockIdx.x, t = threadIdx.x;
    int base = b * SCAN_BLK;
    int c[4], local = 0;
    #pragma unroll
    for (int i = 0; i < 4; i++) {
        int g = base + t * 4 + i;
        c[i] = (g < n) ? g_count[g] : 0;
        local += c[i];
    }
    s[t] = local; __syncthreads();
    for (int o = 1; o < 256; o <<= 1) {      // inclusive Hillis-Steele
        int v = (t >= o) ? s[t - o] : 0;
        __syncthreads();
        s[t] += v;
        __syncthreads();
    }
    int excl = (t > 0 ? s[t - 1] : 0) + g_bsum[b];
    #pragma unroll
    for (int i = 0; i < 4; i++) {
        int g = base + t * 4 + i;
        if (g < n) { g_base[g] = excl; g_cursor[g] = excl; }
        excl += c[i];
    }
}

__global__ void k_scatter(const int* __restrict__ idx, int H) {
    int h = blockIdx.x * blockDim.x + threadIdx.x;
    if (h < H) {
        int n = idx[h];
        int p = atomicAdd(&g_cursor[n], 1);
        g_perm[p] = h;
    }
}

// Main: one warp per node. Row read once (32 lanes x 16B), stored to every
// destination half-row (512B contiguous per store, coalesced per warp).
__global__ void __launch_bounds__(256) k_broadcast(
    const float4* __restrict__ X, float4* __restrict__ out, int N)
{
    int w = (blockIdx.x * blockDim.x + threadIdx.x) >> 5;
    int lane = threadIdx.x & 31;
    if (w >= N) return;
    int start = g_base[w];
    int end = start + g_count[w];
    if (start == end) return;

    float4 v = __ldg(&X[(long long)w * D4 + lane]);  // the one row read

    for (int j0 = start; j0 < end; j0 += 32) {
        int m = min(32, end - j0);
        int h = (lane < m) ? g_perm[j0 + lane] : 0;  // coalesced list read
        for (int k = 0; k < m; k++) {
            int hk = __shfl_sync(0xffffffffu, h, k);
            __stcs(&out[(long long)hk * D4 + lane], v);
        }
    }
}

// Fallback direct gather (only if shapes exceed scratch; never at bench shape)
__global__ void __launch_bounds__(256) k_direct(
    const float4* __restrict__ X, const int* __restrict__ idx,
    float4* __restrict__ out, int total_chunks)
{
    int t = blockIdx.x * blockDim.x + threadIdx.x;
    if (t >= total_chunks) return;
    int h = t >> 5;
    int c = t & 31;
    int node = __ldg(&idx[h]);
    __stcs(&out[t], __ldg(&X[(long long)node * D4 + c]));
}

extern "C" void kernel_launch(void* const* d_in, const int* in_sizes, int n_in,
                              void* d_out, int out_size)
{
    const float4* X = (const float4*)d_in[0];
    const int* idx = (const int*)d_in[1];
    float4* out = (float4*)d_out;

    int N = in_sizes[0] / 128;    // nodes
    int H = in_sizes[1];          // 2E half-rows

    if (N > N_MAX || H > H_MAX) {
        int total = H * D4;
        k_direct<<<(total + 255) / 256, 256>>>(X, idx, out, total);
        return;
    }

    int nb = (N + SCAN_BLK - 1) / SCAN_BLK;

    k_zero   <<<(N + 255) / 256, 256>>>(N);
    k_hist   <<<(H + 255) / 256, 256>>>(idx, H);
    k_scanA  <<<nb, 256>>>(N);
    k_scanB  <<<1, 32>>>(nb);
    k_scanC  <<<nb, 256>>>(N);
    k_scatter<<<(H + 255) / 256, 256>>>(idx, H);

    long long threads = (long long)N * 32;
    k_broadcast<<<(int)((threads + 255) / 256), 256>>>(X, out, N);
}

// round 9
// speedup vs baseline: 1.1368x; 1.1368x over previous
#include <cuda_runtime.h>

// out_half[h] = X[idx_flat[h], :]  (512B per half-row), h in [0, 2E)
// Inverted mapping with fixed-capacity buckets:
//   fill:      slot[n*CAP + atomicAdd(cnt[n],1)] = h   (overflow: direct copy)
//   broadcast: warp w loads X[w] once (32x16B) and stores it to every
//              destination half-row in its bucket (512B coalesced stores).
// LTS traffic: ~328MB wr + 51MB X rd + ~10MB meta  vs 656MB for plain gather.

#define D4 32                 // float4 per X row
#define N_MAX 131072
#define CAP 64
#define H_MAX (1 << 20)

__device__ int g_cnt[N_MAX];
__device__ int g_slot[N_MAX * CAP];     // 32 MB scratch (static, allowed)

__global__ void k_zero(int n) {
    int i = blockIdx.x * blockDim.x + threadIdx.x;
    if (i < n) g_cnt[i] = 0;
}

__global__ void __launch_bounds__(256) k_fill(
    const int* __restrict__ idx,
    const float4* __restrict__ X,
    float4* __restrict__ out,
    int H)
{
    int h = blockIdx.x * blockDim.x + threadIdx.x;
    if (h >= H) return;
    int n = __ldg(&idx[h]);
    int p = atomicAdd(&g_cnt[n], 1);
    if (p < CAP) {
        g_slot[n * CAP + p] = h;
    } else {
        // Overflow (never at bench shape): this edge copies its row directly.
        const float4* src = &X[(long long)n * D4];
        float4* dst = &out[(long long)h * D4];
        #pragma unroll
        for (int c = 0; c < D4; c++) __stcs(&dst[c], __ldg(&src[c]));
    }
}

// One warp per node: read row once, broadcast-store to all destinations.
__global__ void __launch_bounds__(256) k_broadcast(
    const float4* __restrict__ X, float4* __restrict__ out, int N)
{
    int w = (blockIdx.x * blockDim.x + threadIdx.x) >> 5;
    int lane = threadIdx.x & 31;
    if (w >= N) return;

    int cnt = __ldg(&g_cnt[w]);             // warp-uniform broadcast load
    if (cnt == 0) return;
    int m = min(cnt, CAP);

    float4 v = __ldg(&X[(long long)w * D4 + lane]);   // the one row read

    const int* bucket = &g_slot[w * CAP];
    for (int j0 = 0; j0 < m; j0 += 32) {
        int nm = min(32, m - j0);
        int h = (lane < nm) ? __ldg(&bucket[j0 + lane]) : 0;  // coalesced
        #pragma unroll 4
        for (int k = 0; k < nm; k++) {
            int hk = __shfl_sync(0xffffffffu, h, k);
            __stcs(&out[(long long)hk * D4 + lane], v);
        }
    }
}

// Fallback direct gather (only if shapes exceed scratch; never at bench shape)
__global__ void __launch_bounds__(256) k_direct(
    const float4* __restrict__ X, const int* __restrict__ idx,
    float4* __restrict__ out, int total_chunks)
{
    int t = blockIdx.x * blockDim.x + threadIdx.x;
    if (t >= total_chunks) return;
    int h = t >> 5;
    int c = t & 31;
    int node = __ldg(&idx[h]);
    __stcs(&out[t], __ldg(&X[(long long)node * D4 + c]));
}

extern "C" void kernel_launch(void* const* d_in, const int* in_sizes, int n_in,
                              void* d_out, int out_size)
{
    const float4* X = (const float4*)d_in[0];
    const int* idx = (const int*)d_in[1];
    float4* out = (float4*)d_out;

    int N = in_sizes[0] / 128;    // nodes
    int H = in_sizes[1];          // 2E half-rows

    if (N > N_MAX || H > H_MAX) {
        int total = H * D4;
        k_direct<<<(total + 255) / 256, 256>>>(X, idx, out, total);
        return;
    }

    k_zero<<<(N + 255) / 256, 256>>>(N);
    k_fill<<<(H + 255) / 256, 256>>>(idx, X, out, H);

    long long threads = (long long)N * 32;
    k_broadcast<<<(int)((threads + 255) / 256), 256>>>(X, out, N);
}

// round 12
// speedup vs baseline: 1.2704x; 1.1175x over previous
#include <cuda_runtime.h>
#include <cstdint>

// out[e, 0:128] = X[src[e], :] ; out[e, 128:256] = X[dst[e], :]
// X: [N,128] fp32 (512B rows, 51.2MB -> fits L2)  idx: [E,2] int32  out: [E,256] fp32
//
// R4 structure (8 float4 chunks/thread; warp covers one 512B source row:
// warp-uniform idx load + 4x128B coalesced gather; linear .cs stores).
// X/idx reads carry an L2::evict_last policy (createpolicy + cache_hint,
// the encoding sm_103a ptxas accepts for sub-256b loads) so the X table
// stays L2-resident across graph replays instead of being flushed by the
// evict-first write stream.

#define CPT 8

__device__ __forceinline__ uint64_t make_evict_last_policy() {
    uint64_t pol;
    asm("createpolicy.fractional.L2::evict_last.b64 %0, 1.0;" : "=l"(pol));
    return pol;
}

__device__ __forceinline__ float4 ldg_el4(const float4* p, uint64_t pol) {
    float4 v;
    asm("ld.global.nc.L2::cache_hint.v4.f32 {%0,%1,%2,%3}, [%4], %5;"
        : "=f"(v.x), "=f"(v.y), "=f"(v.z), "=f"(v.w)
        : "l"(p), "l"(pol));
    return v;
}

__device__ __forceinline__ int ldg_el_i(const int* p, uint64_t pol) {
    int v;
    asm("ld.global.nc.L2::cache_hint.b32 %0, [%1], %2;"
        : "=r"(v) : "l"(p), "l"(pol));
    return v;
}

__global__ void __launch_bounds__(256) link_embed_gather_kernel(
    const char* __restrict__ Xb,        // byte pointer to X
    const int* __restrict__ idx,
    float4* __restrict__ out,
    int total_chunks)   // E * 64
{
    const int stride = gridDim.x * blockDim.x;
    const int t0 = blockIdx.x * blockDim.x + threadIdx.x;
    const uint64_t pol = make_evict_last_policy();

    if (t0 + (CPT - 1) * stride < total_chunks) {
        // ---- fast path ----
        unsigned off[CPT];
        #pragma unroll
        for (int i = 0; i < CPT; i++) {
            int t = t0 + i * stride;
            int e = t >> 6;
            int half = (t >> 5) & 1;
            int node = ldg_el_i(&idx[e * 2 + half], pol);     // warp-uniform
            off[i] = ((unsigned)node << 9) | ((unsigned)(t & 31) << 4);
        }

        float4 v[CPT];
        #pragma unroll
        for (int i = 0; i < CPT; i++)
            v[i] = ldg_el4((const float4*)(Xb + off[i]), pol); // sticky in L2

        #pragma unroll
        for (int i = 0; i < CPT; i++)
            __stcs(&out[t0 + i * stride], v[i]);               // evict-first
    } else {
        // ---- guarded tail (not taken at bench shape) ----
        #pragma unroll 4
        for (int i = 0; i < CPT; i++) {
            int t = t0 + i * stride;
            if (t < total_chunks) {
                int e = t >> 6;
                int half = (t >> 5) & 1;
                int node = ldg_el_i(&idx[e * 2 + half], pol);
                unsigned off = ((unsigned)node << 9) | ((unsigned)(t & 31) << 4);
                __stcs(&out[t], ldg_el4((const float4*)(Xb + off), pol));
            }
        }
    }
}

extern "C" void kernel_launch(void* const* d_in, const int* in_sizes, int n_in,
                              void* d_out, int out_size)
{
    const char* Xb = (const char*)d_in[0];
    const int* idx = (const int*)d_in[1];
    float4* out = (float4*)d_out;

    int E = in_sizes[1] / 2;          // indices has E*2 int32 elements
    int total_chunks = E * 64;

    int threads = 256;
    int chunks_per_block = threads * CPT;
    int blocks = (total_chunks + chunks_per_block - 1) / chunks_per_block;
    link_embed_gather_kernel<<<blocks, threads>>>(Xb, idx, out, total_chunks);
}

// round 13
// speedup vs baseline: 1.3003x; 1.0235x over previous
#include <cuda_runtime.h>
#include <cstdint>

// out_half[h] = X[idx[h], :]  (h = e*2+half, 512B per half-row)
// 256-bit (v8.b32) loads+stores: 16 lanes cover one 512B half-row (32B/lane).
// Gathers use direct .L2::evict_last (legal on v8); stores carry an
// evict-first policy. CPT=4 granules/thread -> 128B in flight per thread.

#define CPT 4

struct V8 { unsigned r0,r1,r2,r3,r4,r5,r6,r7; };

__device__ __forceinline__ uint64_t make_evict_first_policy() {
    uint64_t pol;
    asm("createpolicy.fractional.L2::evict_first.b64 %0, 1.0;" : "=l"(pol));
    return pol;
}

__device__ __forceinline__ V8 ldg_v8_el(const void* p) {
    V8 v;
    asm("ld.global.nc.L2::evict_last.v8.b32 {%0,%1,%2,%3,%4,%5,%6,%7}, [%8];"
        : "=r"(v.r0), "=r"(v.r1), "=r"(v.r2), "=r"(v.r3),
          "=r"(v.r4), "=r"(v.r5), "=r"(v.r6), "=r"(v.r7)
        : "l"(p));
    return v;
}

__device__ __forceinline__ void stg_v8_ef(void* p, const V8& v, uint64_t pol) {
    asm volatile("st.global.L2::cache_hint.v8.b32 [%0], {%1,%2,%3,%4,%5,%6,%7,%8}, %9;"
        :: "l"(p),
           "r"(v.r0), "r"(v.r1), "r"(v.r2), "r"(v.r3),
           "r"(v.r4), "r"(v.r5), "r"(v.r6), "r"(v.r7),
           "l"(pol)
        : "memory");
}

__global__ void __launch_bounds__(256) link_embed_gather_kernel(
    const char* __restrict__ Xb,        // byte pointer to X
    const int* __restrict__ idx,        // flat [2E] node ids (== [E,2] layout)
    char* __restrict__ outb,            // byte pointer to out
    int total_granules)                 // 2E * 16 (one 32B granule each)
{
    const int stride = gridDim.x * blockDim.x;
    const int t0 = blockIdx.x * blockDim.x + threadIdx.x;
    const uint64_t pol = make_evict_first_policy();

    if (t0 + (CPT - 1) * stride < total_granules) {
        // ---- fast path (exact at bench shape) ----
        unsigned off[CPT];
        #pragma unroll
        for (int i = 0; i < CPT; i++) {
            int t = t0 + i * stride;
            int h = t >> 4;                       // half-row id
            int node = __ldg(&idx[h]);            // uniform over 16 lanes
            off[i] = ((unsigned)node << 9) | ((unsigned)(t & 15) << 5);
        }

        V8 v[CPT];
        #pragma unroll
        for (int i = 0; i < CPT; i++)
            v[i] = ldg_v8_el(Xb + off[i]);        // 256-bit gather, sticky L2

        #pragma unroll
        for (int i = 0; i < CPT; i++)
            stg_v8_ef(outb + (size_t)(t0 + i * stride) * 32, v[i], pol);
    } else {
        // ---- guarded tail (not taken at bench shape) ----
        #pragma unroll
        for (int i = 0; i < CPT; i++) {
            int t = t0 + i * stride;
            if (t < total_granules) {
                int h = t >> 4;
                int node = __ldg(&idx[h]);
                unsigned off = ((unsigned)node << 9) | ((unsigned)(t & 15) << 5);
                V8 v = ldg_v8_el(Xb + off);
                stg_v8_ef(outb + (size_t)t * 32, v, pol);
            }
        }
    }
}

extern "C" void kernel_launch(void* const* d_in, const int* in_sizes, int n_in,
                              void* d_out, int out_size)
{
    const char* Xb = (const char*)d_in[0];
    const int* idx = (const int*)d_in[1];
    char* outb = (char*)d_out;

    int H = in_sizes[1];                 // 2E half-rows
    int total_granules = H * 16;         // 32B granules

    int threads = 256;
    int per_block = threads * CPT;
    int blocks = (total_granules + per_block - 1) / per_block;
    link_embed_gather_kernel<<<blocks, threads>>>(Xb, idx, outb, total_granules);
}